// round 14
// baseline (speedup 1.0000x reference)
#include <cuda_runtime.h>
#include <cuda_bf16.h>

// Counterfactual neural-ODE in layer-1 PRE-ACTIVATION space (M = W3@W1,
// A = W1^T x). R14: midpoint RK2 over 9-segment steps (99 = 9*11 -> 11
// steps, 22 RHS evals). Stage-2 bias = exact trapezoid mean of the
// treatment (forcing integral exact across interior kinks). Interior-knot
// outputs use a CUBIC HERMITE dense output whose end slope is the NEXT
// step's k1 (f at this step's endpoint). Warp roles: warps 0-1 = serial
// recursion (tanh->L2->Mdot); warp 2 = full-K W3 dots (k1/k2 -> ka/kb);
// warp 3 = dense outputs + x updates + all STGs. Every ka/kb write->read
// pair is separated by an existing __syncthreads.

typedef unsigned long long ull;

__device__ __forceinline__ ull pack2(float lo, float hi) {
    ull r; asm("mov.b64 %0, {%1, %2};" : "=l"(r) : "f"(lo), "f"(hi)); return r;
}
__device__ __forceinline__ ull addf2(ull a, ull b) {
    ull d; asm("add.rn.f32x2 %0, %1, %2;" : "=l"(d) : "l"(a), "l"(b)); return d;
}
__device__ __forceinline__ void ffma2(ull& d, ull a, ull b) {
    asm("fma.rn.f32x2 %0, %1, %2, %3;" : "=l"(d) : "l"(a), "l"(b), "l"(d));
}
__device__ __forceinline__ float hsum(ull v) {
    float lo, hi; asm("mov.b64 {%0, %1}, %2;" : "=f"(lo), "=f"(hi) : "l"(v));
    return lo + hi;
}
__device__ __forceinline__ float hsum4(ull a, ull b, ull c, ull d) {
    return hsum(addf2(addf2(a, b), addf2(c, d)));
}
__device__ __forceinline__ float ftanh(float x) {
    float r; asm("tanh.approx.f32 %0, %1;" : "=f"(r) : "f"(x)); return r;
}

__global__ void __launch_bounds__(128, 1)
ode_fused_kernel(const float* __restrict__ x0,
                 const float* __restrict__ treat,   // [100,4]
                 const float* __restrict__ ts,      // [100]
                 const float* __restrict__ W1,      // [36,64]
                 const float* __restrict__ b1,      // [64]
                 const float* __restrict__ W2,      // [64,64]
                 const float* __restrict__ b2,      // [64]
                 const float* __restrict__ W3,      // [64,32]
                 const float* __restrict__ b3,      // [32]
                 float* __restrict__ out)           // [100,32]
{
    __shared__ __align__(16) float h1b[64];
    __shared__ __align__(16) float h2b[64];
    __shared__ __align__(16) float ka[32];        // k1 of current step
    __shared__ __align__(16) float kb[32];        // k2 of current step
    __shared__ __align__(16) float w3s[2048];     // W3 staged (prologue)
    __shared__ __align__(16) float trb[400];
    __shared__ __align__(16) float4 beP[11 * 64]; // (be1, beM, H, 0) per step
    __shared__ float tsb[104];

    const int t   = threadIdx.x;
    const int tc  = t & 63;          // logical column (compute / bias table)
    const int grp = t >> 6;          // 0 = compute warps, 1 = helper warps
    const int wid = t >> 5;          // warp id: 2 = k-dots, 3 = outputs
    const int l   = t & 31;

    for (int j = t; j < 2048; j += 128) w3s[j] = W3[j];
    for (int j = t; j < 400;  j += 128) trb[j] = treat[j];
    for (int j = t; j < 100;  j += 128) tsb[j] = ts[j];
    if (t < 32) { h1b[t] = x0[t]; h2b[t] = b3[t]; out[t] = x0[t]; }
    __syncthreads();

    const float bb2 = b2[tc];

    float A = 0.0f, c3 = 0.0f;
    ull Mp[32], w2p[32];   // compute-group weights
    ull w3f[32];           // warp-2: full W3 column for output lane l
    float x = 0.0f, bb3w = 0.0f;

    if (grp == 0) {
        // ---- compute-group prologue: W1 col, A0, c3, M = W3@W1 col, W2 col
        ull w1p[16];
#pragma unroll
        for (int j = 0; j < 16; ++j)
            w1p[j] = pack2(W1[(2 * j) * 64 + tc], W1[(2 * j + 1) * 64 + tc]);
        {
            ull a0 = 0, a1 = 0, a2 = 0, a3 = 0, e0 = 0, e1 = 0, e2 = 0, e3 = 0;
            const ulonglong2* sx = (const ulonglong2*)h1b;
            const ulonglong2* sb = (const ulonglong2*)h2b;
#pragma unroll
            for (int q = 0; q < 4; ++q) {
                ulonglong2 vx0 = sx[2 * q], vx1 = sx[2 * q + 1];
                ulonglong2 vb0 = sb[2 * q], vb1 = sb[2 * q + 1];
                ffma2(a0, vx0.x, w1p[4 * q + 0]); ffma2(a1, vx0.y, w1p[4 * q + 1]);
                ffma2(a2, vx1.x, w1p[4 * q + 2]); ffma2(a3, vx1.y, w1p[4 * q + 3]);
                ffma2(e0, vb0.x, w1p[4 * q + 0]); ffma2(e1, vb0.y, w1p[4 * q + 1]);
                ffma2(e2, vb1.x, w1p[4 * q + 2]); ffma2(e3, vb1.y, w1p[4 * q + 3]);
            }
            A  = hsum4(a0, a1, a2, a3);
            c3 = hsum4(e0, e1, e2, e3);
        }
#pragma unroll
        for (int j = 0; j < 32; ++j) {
            ull m0 = 0, m1 = 0, n0 = 0, n1 = 0;
            const ulonglong2* r0 = (const ulonglong2*)(w3s + (2 * j) * 32);
            const ulonglong2* r1 = (const ulonglong2*)(w3s + (2 * j + 1) * 32);
#pragma unroll
            for (int q = 0; q < 4; ++q) {
                ulonglong2 u0 = r0[2 * q], u1 = r0[2 * q + 1];
                ulonglong2 v0 = r1[2 * q], v1 = r1[2 * q + 1];
                ffma2(m0, u0.x, w1p[4 * q + 0]); ffma2(m1, u0.y, w1p[4 * q + 1]);
                ffma2(m0, u1.x, w1p[4 * q + 2]); ffma2(m1, u1.y, w1p[4 * q + 3]);
                ffma2(n0, v0.x, w1p[4 * q + 0]); ffma2(n1, v0.y, w1p[4 * q + 1]);
                ffma2(n0, v1.x, w1p[4 * q + 2]); ffma2(n1, v1.y, w1p[4 * q + 3]);
            }
            Mp[j] = pack2(hsum(addf2(m0, m1)), hsum(addf2(n0, n1)));
        }
#pragma unroll
        for (int j = 0; j < 32; ++j)
            w2p[j] = pack2(W2[(2 * j) * 64 + tc], W2[(2 * j + 1) * 64 + tc]);
    } else {
        // ---- helper prologue: per-step bias/H table (all 64 helper threads)
        const float bb1h = b1[tc];
        const ull w1ta = pack2(W1[32 * 64 + tc], W1[33 * 64 + tc]);
        const ull w1tb = pack2(W1[34 * 64 + tc], W1[35 * 64 + tc]);
#pragma unroll 1
        for (int jj = 0; jj < 11; ++jj) {
            const int base = 9 * jj;
            float s[10];
#pragma unroll
            for (int i = 0; i < 10; ++i) {
                ull u = 0;
                const ulonglong2 v = *(const ulonglong2*)(trb + 4 * (base + i));
                ffma2(u, v.x, w1ta); ffma2(u, v.y, w1tb);
                s[i] = hsum(u);
            }
            float acc = s[0] + s[9];
#pragma unroll
            for (int i = 1; i < 9; ++i) acc += 2.0f * s[i];
            float4 e;
            e.x = bb1h + s[0];                 // be1 (k1 stage)
            e.y = bb1h + acc * (1.0f / 18.0f); // beM (trapezoid-mean stage)
            e.z = tsb[base + 9] - tsb[base];   // H
            e.w = 0.0f;
            beP[jj * 64 + tc] = e;
        }
        if (wid == 2) {
            // full W3 column for output lane l (k = 0..63 in pairs)
#pragma unroll
            for (int j = 0; j < 32; ++j)
                w3f[j] = pack2(W3[(2 * j) * 32 + l], W3[(2 * j + 1) * 32 + l]);
            bb3w = b3[l];
        } else {
            x = x0[l];          // warp 3 owns the reconstructed trajectory
        }
    }
    __syncthreads();   // prologue tables published

    auto layer2 = [&]() {
        ull q0 = pack2(bb2, 0.0f), q1 = 0, q2 = 0, q3 = 0;
        const ulonglong2* hv = (const ulonglong2*)h1b;
#pragma unroll
        for (int q = 0; q < 8; ++q) {
            ulonglong2 v0 = hv[2 * q], v1 = hv[2 * q + 1];
            ffma2(q0, v0.x, w2p[4 * q + 0]); ffma2(q1, v0.y, w2p[4 * q + 1]);
            ffma2(q2, v1.x, w2p[4 * q + 2]); ffma2(q3, v1.y, w2p[4 * q + 3]);
        }
        h2b[tc] = ftanh(hsum4(q0, q1, q2, q3));
    };
    auto gdot = [&]() -> float {     // g = M[:,tc] . h2
        ull d0 = 0, d1 = 0, d2 = 0, d3 = 0;
        const ulonglong2* gv = (const ulonglong2*)h2b;
#pragma unroll
        for (int q = 0; q < 8; ++q) {
            ulonglong2 v0 = gv[2 * q], v1 = gv[2 * q + 1];
            ffma2(d0, v0.x, Mp[4 * q + 0]); ffma2(d1, v0.y, Mp[4 * q + 1]);
            ffma2(d2, v1.x, Mp[4 * q + 2]); ffma2(d3, v1.y, Mp[4 * q + 3]);
        }
        return hsum4(d0, d1, d2, d3);
    };
    auto kfull = [&]() -> float {    // warp 2: k[l] = W3[:,l] . h2 + b3[l]
        ull d0 = 0, d1 = 0, d2 = 0, d3 = 0;
        const ulonglong2* gv = (const ulonglong2*)h2b;
#pragma unroll
        for (int q = 0; q < 8; ++q) {
            ulonglong2 v0 = gv[2 * q], v1 = gv[2 * q + 1];
            ffma2(d0, v0.x, w3f[4 * q + 0]); ffma2(d1, v0.y, w3f[4 * q + 1]);
            ffma2(d2, v1.x, w3f[4 * q + 2]); ffma2(d3, v1.y, w3f[4 * q + 3]);
        }
        return hsum4(d0, d1, d2, d3) + bb3w;
    };

    float4 be = beP[tc];             // step 0 (prefetched thereafter)
    float Hp = 0.0f, k1p = 0.0f, k2p = 0.0f;

#pragma unroll 1
    for (int j = 0; j < 11; ++j) {
        const float H = be.z;

        // ================= eval 1 (k1 at t_base) =================
        if (grp == 0) h1b[tc] = ftanh(A + be.x);
        __syncthreads();                                   // BAR1: h1 ready
        if (grp == 0) {
            layer2();
        } else if (wid == 3 && j > 0) {
            k1p = ka[l];                                   // k1 of step j-1
            k2p = kb[l];                                   // k2 of step j-1
        }
        __syncthreads();                                   // BAR2: h2 ready
        if (grp == 0) {
            const float g1 = gdot();
            const float Amid = fmaf(0.5f * H, g1 + c3, A);
            h1b[tc] = ftanh(Amid + be.y);                  // critical chain
        } else if (wid == 2) {
            ka[l] = kfull();                               // k1 of step j
        }
        __syncthreads();                                   // BAR3: h1 ready

        // ================= eval 2 (k2, averaged treatment) =================
        if (grp == 0) {
            layer2();
        } else if (wid == 3 && j > 0) {
            // finalize step j-1 with cubic Hermite: end slope = k1 of step j
            const float ke = ka[l];
            const float a  = k1p;
            const float b  = 3.0f * k2p - 2.0f * k1p - ke;
            const float cc = k1p + ke - 2.0f * k2p;
            float* o = out + (9 * (j - 1)) * 32 + l;
#pragma unroll
            for (int i = 1; i <= 8; ++i) {
                const float th = (float)i * (1.0f / 9.0f);
                o[i * 32] = fmaf(Hp * th, fmaf(th, fmaf(th, cc, b), a), x);
            }
            x = fmaf(Hp, k2p, x);
            o[9 * 32] = x;
        }
        __syncthreads();                                   // BAR4: h2 ready
        if (grp == 0) {
            const float g2 = gdot();
            A = fmaf(H, g2 + c3, A);                       // critical chain
        } else if (wid == 2) {
            kb[l] = kfull();                               // k2 of step j
        }
        Hp = H;
        be = beP[((j < 10) ? (j + 1) : 10) * 64 + tc];     // prefetch next
    }

    // -------- finalize last step (quadratic dense output, no k_end) --------
    __syncthreads();
    if (wid == 3) {
        const float kq1 = ka[l];
        const float kq2 = kb[l];
        float* o = out + 90 * 32 + l;
#pragma unroll
        for (int i = 1; i <= 8; ++i) {
            const float th = (float)i * (1.0f / 9.0f);
            o[i * 32] = fmaf(Hp, th * (1.0f - th) * kq1 + th * th * kq2, x);
        }
        o[9 * 32] = fmaf(Hp, kq2, x);
    }
}

extern "C" void kernel_launch(void* const* d_in, const int* in_sizes, int n_in,
                              void* d_out, int out_size) {
    const float* x0    = (const float*)d_in[0];
    const float* treat = (const float*)d_in[1];
    const float* ts    = (const float*)d_in[2];
    const float* W1    = (const float*)d_in[3];
    const float* b1    = (const float*)d_in[4];
    const float* W2    = (const float*)d_in[5];
    const float* b2    = (const float*)d_in[6];
    const float* W3    = (const float*)d_in[7];
    const float* b3    = (const float*)d_in[8];
    float* out = (float*)d_out;

    ode_fused_kernel<<<1, 128>>>(x0, treat, ts, W1, b1, W2, b2, W3, b3, out);
}

// round 16
// speedup vs baseline: 1.2979x; 1.2979x over previous
#include <cuda_runtime.h>
#include <cuda_bf16.h>

// Counterfactual neural-ODE in layer-1 PRE-ACTIVATION space (M = W3@W1,
// A = W1^T x). R16 (= R15 re-bench after infra failure, dead w3h removed):
// midpoint RK2 over 9-segment steps (11 steps, 22 evals), stage-2 bias =
// exact trapezoid mean of the treatment; cubic-Hermite dense output (end
// slope = next step's k1). Helper k-dots are SPLIT half-K partials on BOTH
// helper warps (fits the barrier shadows; R14's full-K dot on one warp
// stretched every barrier release). Warp roles: warps 0-1 = serial
// recursion; warps 2+3 = k partials; warp 2 = dense outputs + STGs.

typedef unsigned long long ull;

__device__ __forceinline__ ull pack2(float lo, float hi) {
    ull r; asm("mov.b64 %0, {%1, %2};" : "=l"(r) : "f"(lo), "f"(hi)); return r;
}
__device__ __forceinline__ ull addf2(ull a, ull b) {
    ull d; asm("add.rn.f32x2 %0, %1, %2;" : "=l"(d) : "l"(a), "l"(b)); return d;
}
__device__ __forceinline__ void ffma2(ull& d, ull a, ull b) {
    asm("fma.rn.f32x2 %0, %1, %2, %3;" : "=l"(d) : "l"(a), "l"(b), "l"(d));
}
__device__ __forceinline__ float hsum(ull v) {
    float lo, hi; asm("mov.b64 {%0, %1}, %2;" : "=f"(lo), "=f"(hi) : "l"(v));
    return lo + hi;
}
__device__ __forceinline__ float hsum4(ull a, ull b, ull c, ull d) {
    return hsum(addf2(addf2(a, b), addf2(c, d)));
}
__device__ __forceinline__ float ftanh(float x) {
    float r; asm("tanh.approx.f32 %0, %1;" : "=f"(r) : "f"(x)); return r;
}

__global__ void __launch_bounds__(128, 1)
ode_fused_kernel(const float* __restrict__ x0,
                 const float* __restrict__ treat,   // [100,4]
                 const float* __restrict__ ts,      // [100]
                 const float* __restrict__ W1,      // [36,64]
                 const float* __restrict__ b1,      // [64]
                 const float* __restrict__ W2,      // [64,64]
                 const float* __restrict__ b2,      // [64]
                 const float* __restrict__ W3,      // [64,32]
                 const float* __restrict__ b3,      // [32]
                 float* __restrict__ out)           // [100,32]
{
    __shared__ __align__(16) float h1b[64];
    __shared__ __align__(16) float h2b[64];
    __shared__ __align__(16) float p3a[64];       // k1 half-K partials
    __shared__ __align__(16) float p3b[64];       // k2 half-K partials
    __shared__ __align__(16) float w3s[2048];     // W3 staged (prologue)
    __shared__ __align__(16) float w3t[32 * 68];  // W3 transposed+padded
    __shared__ __align__(16) float trb[400];
    __shared__ __align__(16) float4 beP[11 * 64]; // (be1, beM, H, 0) per step
    __shared__ float tsb[104];

    const int t   = threadIdx.x;
    const int tc  = t & 63;          // logical column within group
    const int grp = t >> 6;          // 0 = compute warps, 1 = helper warps
    const int wid = t >> 5;          // warp id (2 = output warp)
    const int l   = t & 31;
    const int i3  = tc & 31;
    const int kh  = tc >> 5;

    for (int j = t; j < 2048; j += 128) w3s[j] = W3[j];
    for (int j = t; j < 400;  j += 128) trb[j] = treat[j];
    for (int j = t; j < 100;  j += 128) tsb[j] = ts[j];
    if (t < 32) { h1b[t] = x0[t]; h2b[t] = b3[t]; out[t] = x0[t]; }
    __syncthreads();

    const float bb2 = b2[tc];

    float A = 0.0f, c3 = 0.0f;
    ull Mp[32], w2p[32];   // compute-group weights
    float x = 0.0f, bb3w = 0.0f;

    if (grp == 0) {
        // ---- compute prologue. All LDGs issued first; Mp math hides them.
        ull w1p[16];
#pragma unroll
        for (int j = 0; j < 16; ++j)
            w1p[j] = pack2(W1[(2 * j) * 64 + tc], W1[(2 * j + 1) * 64 + tc]);
#pragma unroll
        for (int j = 0; j < 32; ++j)
            w2p[j] = pack2(W2[(2 * j) * 64 + tc], W2[(2 * j + 1) * 64 + tc]);
        {
            ull a0 = 0, a1 = 0, a2 = 0, a3 = 0, e0 = 0, e1 = 0, e2 = 0, e3 = 0;
            const ulonglong2* sx = (const ulonglong2*)h1b;
            const ulonglong2* sb = (const ulonglong2*)h2b;
#pragma unroll
            for (int q = 0; q < 4; ++q) {
                ulonglong2 vx0 = sx[2 * q], vx1 = sx[2 * q + 1];
                ulonglong2 vb0 = sb[2 * q], vb1 = sb[2 * q + 1];
                ffma2(a0, vx0.x, w1p[4 * q + 0]); ffma2(a1, vx0.y, w1p[4 * q + 1]);
                ffma2(a2, vx1.x, w1p[4 * q + 2]); ffma2(a3, vx1.y, w1p[4 * q + 3]);
                ffma2(e0, vb0.x, w1p[4 * q + 0]); ffma2(e1, vb0.y, w1p[4 * q + 1]);
                ffma2(e2, vb1.x, w1p[4 * q + 2]); ffma2(e3, vb1.y, w1p[4 * q + 3]);
            }
            A  = hsum4(a0, a1, a2, a3);
            c3 = hsum4(e0, e1, e2, e3);
        }
#pragma unroll
        for (int j = 0; j < 32; ++j) {
            ull m0 = 0, m1 = 0, n0 = 0, n1 = 0;
            const ulonglong2* r0 = (const ulonglong2*)(w3s + (2 * j) * 32);
            const ulonglong2* r1 = (const ulonglong2*)(w3s + (2 * j + 1) * 32);
#pragma unroll
            for (int q = 0; q < 4; ++q) {
                ulonglong2 u0 = r0[2 * q], u1 = r0[2 * q + 1];
                ulonglong2 v0 = r1[2 * q], v1 = r1[2 * q + 1];
                ffma2(m0, u0.x, w1p[4 * q + 0]); ffma2(m1, u0.y, w1p[4 * q + 1]);
                ffma2(m0, u1.x, w1p[4 * q + 2]); ffma2(m1, u1.y, w1p[4 * q + 3]);
                ffma2(n0, v0.x, w1p[4 * q + 0]); ffma2(n1, v0.y, w1p[4 * q + 1]);
                ffma2(n0, v1.x, w1p[4 * q + 2]); ffma2(n1, v1.y, w1p[4 * q + 3]);
            }
            Mp[j] = pack2(hsum(addf2(m0, m1)), hsum(addf2(n0, n1)));
        }
    } else {
        // ---- helper prologue: W3 transpose, bias/H table
        const float bb1h = b1[tc];
        const ull w1ta = pack2(W1[32 * 64 + tc], W1[33 * 64 + tc]);
        const ull w1tb = pack2(W1[34 * 64 + tc], W1[35 * 64 + tc]);
        for (int j = tc; j < 2048; j += 64) {
            int k = j >> 5, i = j & 31;
            w3t[i * 68 + k] = w3s[j];
        }
#pragma unroll 1
        for (int jj = 0; jj < 11; ++jj) {
            const int base = 9 * jj;
            float s[10];
#pragma unroll
            for (int i = 0; i < 10; ++i) {
                ull u = 0;
                const ulonglong2 v = *(const ulonglong2*)(trb + 4 * (base + i));
                ffma2(u, v.x, w1ta); ffma2(u, v.y, w1tb);
                s[i] = hsum(u);
            }
            float acc = s[0] + s[9];
#pragma unroll
            for (int i = 1; i < 9; ++i) acc += 2.0f * s[i];
            float4 e;
            e.x = bb1h + s[0];                 // be1 (k1 stage)
            e.y = bb1h + acc * (1.0f / 18.0f); // beM (trapezoid-mean stage)
            e.z = tsb[base + 9] - tsb[base];   // H
            e.w = 0.0f;
            beP[jj * 64 + tc] = e;
        }
        if (wid == 2) { x = x0[l]; bb3w = b3[l]; }
    }
    __syncthreads();   // prologue tables published

    const ulonglong2* pw = (const ulonglong2*)(w3t + i3 * 68 + kh * 32);

    auto layer2 = [&]() {
        ull q0 = pack2(bb2, 0.0f), q1 = 0, q2 = 0, q3 = 0;
        const ulonglong2* hv = (const ulonglong2*)h1b;
#pragma unroll
        for (int q = 0; q < 8; ++q) {
            ulonglong2 v0 = hv[2 * q], v1 = hv[2 * q + 1];
            ffma2(q0, v0.x, w2p[4 * q + 0]); ffma2(q1, v0.y, w2p[4 * q + 1]);
            ffma2(q2, v1.x, w2p[4 * q + 2]); ffma2(q3, v1.y, w2p[4 * q + 3]);
        }
        h2b[tc] = ftanh(hsum4(q0, q1, q2, q3));
    };
    auto gdot = [&]() -> float {     // g = M[:,tc] . h2
        ull d0 = 0, d1 = 0, d2 = 0, d3 = 0;
        const ulonglong2* gv = (const ulonglong2*)h2b;
#pragma unroll
        for (int q = 0; q < 8; ++q) {
            ulonglong2 v0 = gv[2 * q], v1 = gv[2 * q + 1];
            ffma2(d0, v0.x, Mp[4 * q + 0]); ffma2(d1, v0.y, Mp[4 * q + 1]);
            ffma2(d2, v1.x, Mp[4 * q + 2]); ffma2(d3, v1.y, Mp[4 * q + 3]);
        }
        return hsum4(d0, d1, d2, d3);
    };
    auto pdot = [&](float* dst) {    // half-K W3 partial (both helper warps)
        ull p0 = 0, p1 = 0;
        const ulonglong2* ph = (const ulonglong2*)(h2b + kh * 32);
#pragma unroll
        for (int q = 0; q < 8; ++q) {
            ulonglong2 wv = pw[q], hv = ph[q];
            ffma2(p0, hv.x, wv.x);
            ffma2(p1, hv.y, wv.y);
        }
        dst[tc] = hsum(addf2(p0, p1));
    };

    float4 be = beP[tc];             // step 0 (prefetched thereafter)
    float Hp = 0.0f, k1p = 0.0f, k2p = 0.0f;

#pragma unroll 1
    for (int j = 0; j < 11; ++j) {
        const float H = be.z;

        // ================= eval 1 (k1 at t_base) =================
        if (grp == 0) h1b[tc] = ftanh(A + be.x);
        __syncthreads();                                   // BAR1: h1 ready
        if (grp == 0) {
            layer2();
        } else if (wid == 2 && j > 0) {
            k1p = p3a[l] + p3a[l + 32] + bb3w;             // step j-1 k1
            k2p = p3b[l] + p3b[l + 32] + bb3w;             // step j-1 k2
        }
        __syncthreads();                                   // BAR2: h2 ready
        if (grp == 0) {
            const float g1 = gdot();
            const float Amid = fmaf(0.5f * H, g1 + c3, A);
            h1b[tc] = ftanh(Amid + be.y);                  // critical chain
        } else {
            pdot(p3a);                                     // k1 half partial
        }
        __syncthreads();                                   // BAR3: h1 ready

        // ================= eval 2 (k2, averaged treatment) =================
        if (grp == 0) {
            layer2();
        } else if (wid == 2 && j > 0) {
            // finalize step j-1: cubic Hermite, end slope = k1 of step j
            const float ke = p3a[l] + p3a[l + 32] + bb3w;
            const float a  = k1p;
            const float b  = 3.0f * k2p - 2.0f * k1p - ke;
            const float cc = k1p + ke - 2.0f * k2p;
            float* o = out + (9 * (j - 1)) * 32 + l;
#pragma unroll
            for (int i = 1; i <= 8; ++i) {
                const float th = (float)i * (1.0f / 9.0f);
                o[i * 32] = fmaf(Hp * th, fmaf(th, fmaf(th, cc, b), a), x);
            }
            x = fmaf(Hp, k2p, x);
            o[9 * 32] = x;
        }
        __syncthreads();                                   // BAR4: h2 ready
        if (grp == 0) {
            const float g2 = gdot();
            A = fmaf(H, g2 + c3, A);                       // critical chain
        } else {
            pdot(p3b);                                     // k2 half partial
        }
        Hp = H;
        be = beP[((j < 10) ? (j + 1) : 10) * 64 + tc];     // prefetch next
    }

    // -------- finalize last step (quadratic dense output, no k_end) --------
    __syncthreads();
    if (wid == 2) {
        const float kq1 = p3a[l] + p3a[l + 32] + bb3w;
        const float kq2 = p3b[l] + p3b[l + 32] + bb3w;
        float* o = out + 90 * 32 + l;
#pragma unroll
        for (int i = 1; i <= 8; ++i) {
            const float th = (float)i * (1.0f / 9.0f);
            o[i * 32] = fmaf(Hp, th * (1.0f - th) * kq1 + th * th * kq2, x);
        }
        o[9 * 32] = fmaf(Hp, kq2, x);
    }
}

extern "C" void kernel_launch(void* const* d_in, const int* in_sizes, int n_in,
                              void* d_out, int out_size) {
    const float* x0    = (const float*)d_in[0];
    const float* treat = (const float*)d_in[1];
    const float* ts    = (const float*)d_in[2];
    const float* W1    = (const float*)d_in[3];
    const float* b1    = (const float*)d_in[4];
    const float* W2    = (const float*)d_in[5];
    const float* b2    = (const float*)d_in[6];
    const float* W3    = (const float*)d_in[7];
    const float* b3    = (const float*)d_in[8];
    float* out = (float*)d_out;

    ode_fused_kernel<<<1, 128>>>(x0, treat, ts, W1, b1, W2, b2, W3, b3, out);
}